// round 4
// baseline (speedup 1.0000x reference)
#include <cuda_runtime.h>
#include <cstdint>

#define NNODES 100000
#define TT 7
#define KK 10
#define DD 7
#define OO 32
#define HET ((TT + 1) * DD)        // 56
#define BLOCK 64
#define GRID ((NNODES + BLOCK - 1) / BLOCK)   // 1563
#define NODE_F (KK * DD)           // 70 floats per node per type
#define TILE_F (BLOCK * NODE_F)    // 4480 floats = 17920 B per tile buffer

// deterministic per-block partial sums + completion counter (zero-init at load)
__device__ float g_partial[GRID * OO];
__device__ unsigned int g_count;

__device__ __forceinline__ void cp_async16(uint32_t smem, const void* gmem) {
    asm volatile("cp.async.ca.shared.global [%0], [%1], 16;\n" :: "r"(smem), "l"(gmem));
}
__device__ __forceinline__ void cp_commit() {
    asm volatile("cp.async.commit_group;\n" ::: "memory");
}
template <int N>
__device__ __forceinline__ void cp_wait() {
    asm volatile("cp.async.wait_group %0;\n" :: "n"(N) : "memory");
}

__global__ __launch_bounds__(BLOCK) void hetgcn_main(
    const float* __restrict__ x_node,      // [N, D]
    const float* __restrict__ x_het,       // [T, N, K, D]
    const int*   __restrict__ node_types,  // [N]
    const float* __restrict__ W_content,   // [T, D, D]
    const float* __restrict__ b_content,   // [T, D]
    const float* __restrict__ W_agg,       // [O, HET]
    const float* __restrict__ b_agg)       // [O]
{
    __shared__ __align__(16) float sx[2][TILE_F];   // 35840 B double-buffered tile
    __shared__ float sW[TT * DD * DD];              // 1372 B
    __shared__ float sb[TT * DD];                   // 196 B
    __shared__ float wsum[2][OO];                   // 256 B
    __shared__ int   s_last;

    const int tid = threadIdx.x;
    const int n0  = blockIdx.x * BLOCK;
    const int n   = n0 + tid;
    const bool active = (n < NNODES);
    const int rows   = min(BLOCK, NNODES - n0);
    const int chunks = rows * NODE_F / 4;           // 16B chunks (rows even)

    for (int i = tid; i < TT * DD * DD; i += BLOCK) sW[i] = W_content[i];
    for (int i = tid; i < TT * DD;     i += BLOCK) sb[i] = b_content[i];

    // prefetch tile 0  (base byte offset is 16B aligned: (t*N+n0) even, *280)
    {
        const float* src = x_het + (size_t)n0 * NODE_F;
        uint32_t dst = (uint32_t)__cvta_generic_to_shared(&sx[0][0]);
        for (int c = tid; c < chunks; c += BLOCK)
            cp_async16(dst + c * 16, src + c * 4);
        cp_commit();
    }

    float het[HET];

    #pragma unroll
    for (int t = 0; t < TT; ++t) {
        if (t + 1 < TT) {   // prefetch next type's tile into the other buffer
            const float* src = x_het + ((size_t)(t + 1) * NNODES + n0) * NODE_F;
            uint32_t dst = (uint32_t)__cvta_generic_to_shared(&sx[(t + 1) & 1][0]);
            for (int c = tid; c < chunks; c += BLOCK)
                cp_async16(dst + c * 16, src + c * 4);
            cp_commit();
        }
        if (t + 1 < TT) cp_wait<1>(); else cp_wait<0>();
        __syncthreads();

        float Wr[DD * DD], br[DD];
        #pragma unroll
        for (int i = 0; i < DD * DD; ++i) Wr[i] = sW[t * DD * DD + i];
        #pragma unroll
        for (int i = 0; i < DD; ++i) br[i] = sb[t * DD + i];

        float acc[DD];
        #pragma unroll
        for (int o = 0; o < DD; ++o) acc[o] = 0.f;
        float cnt = 0.f;

        const float* xs = &sx[t & 1][tid * NODE_F];
        #pragma unroll 2
        for (int k = 0; k < KK; ++k) {
            float xv[DD];
            #pragma unroll
            for (int d = 0; d < DD; ++d) xv[d] = xs[k * DD + d];
            bool nz = false;
            #pragma unroll
            for (int o = 0; o < DD; ++o) {
                float z = br[o];
                #pragma unroll
                for (int d = 0; d < DD; ++d) z = fmaf(xv[d], Wr[o * DD + d], z);
                float e = fmaxf(z, 0.01f * z);      // LeakyReLU (z<0 -> 0.01z)
                nz = nz || (z != 0.f);              // e!=0  <=>  z!=0
                acc[o] += e;                        // masked rows are all-zero
            }
            if (nz) cnt += 1.f;
        }
        const float inv = 1.f / fmaxf(cnt, 1.f);
        #pragma unroll
        for (int o = 0; o < DD; ++o) het[t * DD + o] = acc[o] * inv;

        __syncthreads();   // everyone done with buf (t&1) before refill at t+1
    }

    // self embedding with the node's own type-specific linear
    {
        const int ty = active ? node_types[n] : 0;
        float xn[DD];
        #pragma unroll
        for (int d = 0; d < DD; ++d) xn[d] = active ? x_node[n * DD + d] : 0.f;
        #pragma unroll
        for (int o = 0; o < DD; ++o) {
            float z = sb[ty * DD + o];
            #pragma unroll
            for (int d = 0; d < DD; ++d) z = fmaf(xn[d], sW[ty * DD * DD + o * DD + d], z);
            het[TT * DD + o] = fmaxf(z, 0.01f * z);
        }
    }

    // final GEMV (56 -> 32) + sigmoid + warp butterfly reduction
    // W_agg read directly from gmem: warp-uniform float4 broadcasts (L1-hot)
    const float4* w4 = (const float4*)W_agg;       // rows are 224B, 16B aligned
    const int wid = tid >> 5, lane = tid & 31;
    for (int o = 0; o < OO; ++o) {
        float z = __ldg(&b_agg[o]);
        #pragma unroll
        for (int j = 0; j < HET / 4; ++j) {
            float4 w = __ldg(&w4[o * (HET / 4) + j]);
            z = fmaf(het[4 * j + 0], w.x, z);
            z = fmaf(het[4 * j + 1], w.y, z);
            z = fmaf(het[4 * j + 2], w.z, z);
            z = fmaf(het[4 * j + 3], w.w, z);
        }
        float y = active ? (1.f / (1.f + __expf(-z))) : 0.f;
        #pragma unroll
        for (int off = 16; off > 0; off >>= 1)
            y += __shfl_xor_sync(0xffffffffu, y, off);
        if (lane == 0) wsum[wid][o] = y;
    }
    __syncthreads();
    if (tid < OO)
        g_partial[blockIdx.x * OO + tid] = wsum[0][tid] + wsum[1][tid];

    // ---- fused deterministic finale: last block reduces all partials ----
    __threadfence();
    if (tid == 0) {
        unsigned int prev = atomicAdd(&g_count, 1u);
        s_last = (prev == GRID - 1u) ? 1 : 0;
    }
    __syncthreads();
    if (s_last) {
        __threadfence();
        const volatile float* gp = g_partial;
        const int o = tid & 31;
        const int h = tid >> 5;                    // 0 or 1
        float a0 = 0.f, a1 = 0.f, a2 = 0.f, a3 = 0.f;
        int b = h;
        for (; b + 6 < GRID; b += 8) {             // 8-way stride, 4 accumulators x2
            a0 += gp[(b    ) * OO + o];
            a1 += gp[(b + 2) * OO + o];
            a2 += gp[(b + 4) * OO + o];
            a3 += gp[(b + 6) * OO + o];
        }
        for (; b < GRID; b += 2) a0 += gp[b * OO + o];
        wsum[h][o] = (a0 + a1) + (a2 + a3);
        __syncthreads();
        if (tid < OO) {
            float* out = (float*)((void**)0 == 0 ? nullptr : nullptr); // placeholder removed below
        }
    }
}

// thin epilogue writer: last block stored its result into wsum (shared) — but
// shared memory dies with the block, so the finale writes d_out directly.
// To keep one kernel, hetgcn_main needs d_out; wrapper below passes it.

__global__ __launch_bounds__(BLOCK) void hetgcn_dummy() {}

extern "C" void kernel_launch(void* const* d_in, const int* in_sizes, int n_in,
                              void* d_out, int out_size);

// --- real implementation: main kernel takes d_out and finishes the job ---
__global__ __launch_bounds__(BLOCK) void hetgcn_fused(
    const float* __restrict__ x_node,
    const float* __restrict__ x_het,
    const int*   __restrict__ node_types,
    const float* __restrict__ W_content,
    const float* __restrict__ b_content,
    const float* __restrict__ W_agg,
    const float* __restrict__ b_agg,
    float* __restrict__ out)
{
    __shared__ __align__(16) float sx[2][TILE_F];
    __shared__ float sW[TT * DD * DD];
    __shared__ float sb[TT * DD];
    __shared__ float wsum[2][OO];
    __shared__ int   s_last;

    const int tid = threadIdx.x;
    const int n0  = blockIdx.x * BLOCK;
    const int n   = n0 + tid;
    const bool active = (n < NNODES);
    const int rows   = min(BLOCK, NNODES - n0);
    const int chunks = rows * NODE_F / 4;

    for (int i = tid; i < TT * DD * DD; i += BLOCK) sW[i] = W_content[i];
    for (int i = tid; i < TT * DD;     i += BLOCK) sb[i] = b_content[i];

    {
        const float* src = x_het + (size_t)n0 * NODE_F;
        uint32_t dst = (uint32_t)__cvta_generic_to_shared(&sx[0][0]);
        for (int c = tid; c < chunks; c += BLOCK)
            cp_async16(dst + c * 16, src + c * 4);
        cp_commit();
    }

    float het[HET];

    #pragma unroll
    for (int t = 0; t < TT; ++t) {
        if (t + 1 < TT) {
            const float* src = x_het + ((size_t)(t + 1) * NNODES + n0) * NODE_F;
            uint32_t dst = (uint32_t)__cvta_generic_to_shared(&sx[(t + 1) & 1][0]);
            for (int c = tid; c < chunks; c += BLOCK)
                cp_async16(dst + c * 16, src + c * 4);
            cp_commit();
        }
        if (t + 1 < TT) cp_wait<1>(); else cp_wait<0>();
        __syncthreads();

        float Wr[DD * DD], br[DD];
        #pragma unroll
        for (int i = 0; i < DD * DD; ++i) Wr[i] = sW[t * DD * DD + i];
        #pragma unroll
        for (int i = 0; i < DD; ++i) br[i] = sb[t * DD + i];

        float acc[DD];
        #pragma unroll
        for (int o = 0; o < DD; ++o) acc[o] = 0.f;
        float cnt = 0.f;

        const float* xs = &sx[t & 1][tid * NODE_F];
        #pragma unroll 2
        for (int k = 0; k < KK; ++k) {
            float xv[DD];
            #pragma unroll
            for (int d = 0; d < DD; ++d) xv[d] = xs[k * DD + d];
            bool nz = false;
            #pragma unroll
            for (int o = 0; o < DD; ++o) {
                float z = br[o];
                #pragma unroll
                for (int d = 0; d < DD; ++d) z = fmaf(xv[d], Wr[o * DD + d], z);
                float e = fmaxf(z, 0.01f * z);
                nz = nz || (z != 0.f);
                acc[o] += e;
            }
            if (nz) cnt += 1.f;
        }
        const float inv = 1.f / fmaxf(cnt, 1.f);
        #pragma unroll
        for (int o = 0; o < DD; ++o) het[t * DD + o] = acc[o] * inv;

        __syncthreads();
    }

    {
        const int ty = active ? node_types[n] : 0;
        float xn[DD];
        #pragma unroll
        for (int d = 0; d < DD; ++d) xn[d] = active ? x_node[n * DD + d] : 0.f;
        #pragma unroll
        for (int o = 0; o < DD; ++o) {
            float z = sb[ty * DD + o];
            #pragma unroll
            for (int d = 0; d < DD; ++d) z = fmaf(xn[d], sW[ty * DD * DD + o * DD + d], z);
            het[TT * DD + o] = fmaxf(z, 0.01f * z);
        }
    }

    const float4* w4 = (const float4*)W_agg;
    const int wid = tid >> 5, lane = tid & 31;
    for (int o = 0; o < OO; ++o) {
        float z = __ldg(&b_agg[o]);
        #pragma unroll
        for (int j = 0; j < HET / 4; ++j) {
            float4 w = __ldg(&w4[o * (HET / 4) + j]);
            z = fmaf(het[4 * j + 0], w.x, z);
            z = fmaf(het[4 * j + 1], w.y, z);
            z = fmaf(het[4 * j + 2], w.z, z);
            z = fmaf(het[4 * j + 3], w.w, z);
        }
        float y = active ? (1.f / (1.f + __expf(-z))) : 0.f;
        #pragma unroll
        for (int off = 16; off > 0; off >>= 1)
            y += __shfl_xor_sync(0xffffffffu, y, off);
        if (lane == 0) wsum[wid][o] = y;
    }
    __syncthreads();
    if (tid < OO)
        g_partial[blockIdx.x * OO + tid] = wsum[0][tid] + wsum[1][tid];

    // fused deterministic finale: the last-arriving block sums all partials.
    __threadfence();
    if (tid == 0) {
        unsigned int prev = atomicAdd(&g_count, 1u);
        s_last = (prev == (unsigned)(GRID - 1)) ? 1 : 0;
    }
    __syncthreads();
    if (s_last) {
        __threadfence();
        const volatile float* gp = g_partial;
        const int o = tid & 31;
        const int h = tid >> 5;                 // 0 or 1
        float a0 = 0.f, a1 = 0.f, a2 = 0.f, a3 = 0.f;
        int b = h;
        for (; b + 6 < GRID; b += 8) {
            a0 += gp[(b    ) * OO + o];
            a1 += gp[(b + 2) * OO + o];
            a2 += gp[(b + 4) * OO + o];
            a3 += gp[(b + 6) * OO + o];
        }
        for (; b < GRID; b += 2) a0 += gp[b * OO + o];
        wsum[h][o] = (a0 + a1) + (a2 + a3);
        __syncthreads();
        if (tid < OO)
            out[tid] = (wsum[0][tid] + wsum[1][tid]) * (1.0f / (float)NNODES);
        if (tid == 0) g_count = 0;              // reset for next graph replay
    }
}

extern "C" void kernel_launch(void* const* d_in, const int* in_sizes, int n_in,
                              void* d_out, int out_size)
{
    const float* x_node    = (const float*)d_in[0];
    const float* x_het     = (const float*)d_in[1];
    const int*   types     = (const int*)  d_in[2];
    const float* W_content = (const float*)d_in[3];
    const float* b_content = (const float*)d_in[4];
    const float* W_agg     = (const float*)d_in[5];
    const float* b_agg     = (const float*)d_in[6];
    float* out = (float*)d_out;

    hetgcn_fused<<<GRID, BLOCK>>>(x_node, x_het, types, W_content, b_content,
                                  W_agg, b_agg, out);
}

// round 5
// speedup vs baseline: 1.1734x; 1.1734x over previous
#include <cuda_runtime.h>
#include <cstdint>

#define NNODES 100000
#define TT 7
#define KK 10
#define DD 7
#define OO 32
#define OP 16                         // 16 packed f32x2 outputs
#define BLOCK 128
#define GRID ((NNODES + BLOCK - 1) / BLOCK)   // 782
#define NODE_B 280                    // bytes per node per type
#define STRA 30                       // padded floats/node, k=0..3 (28 used)  -> 2-way LDS conflict max
#define STRB 46                       // padded floats/node, k=4..9 (42 used)  -> 2-way LDS conflict max

// deterministic per-block partials + completion counter (zero-init at module load)
__device__ float g_partial[GRID * OO];
__device__ unsigned int g_count;

__device__ __forceinline__ void cp8(uint32_t s, const void* g) {
    asm volatile("cp.async.ca.shared.global [%0], [%1], 8;\n" :: "r"(s), "l"(g));
}
__device__ __forceinline__ void cp_commit() { asm volatile("cp.async.commit_group;\n" ::: "memory"); }
template<int N> __device__ __forceinline__ void cp_wait() { asm volatile("cp.async.wait_group %0;\n" :: "n"(N) : "memory"); }

__device__ __forceinline__ unsigned long long pack2(float lo, float hi) {
    unsigned long long d;
    asm("mov.b64 %0, {%1, %2};" : "=l"(d) : "f"(lo), "f"(hi));
    return d;
}
__device__ __forceinline__ float2 unpack2(unsigned long long v) {
    float2 r;
    asm("mov.b64 {%0, %1}, %2;" : "=f"(r.x), "=f"(r.y) : "l"(v));
    return r;
}
__device__ __forceinline__ unsigned long long fma2(unsigned long long a, unsigned long long b, unsigned long long c) {
    unsigned long long d;
    asm("fma.rn.f32x2 %0, %1, %2, %3;" : "=l"(d) : "l"(a), "l"(b), "l"(c));
    return d;
}

__global__ __launch_bounds__(BLOCK, 4) void hetgcn_fused(
    const float* __restrict__ x_node,      // [N, D]
    const float* __restrict__ x_het,       // [T, N, K, D]
    const int*   __restrict__ node_types,  // [N]
    const float* __restrict__ W_content,   // [T, D, D]
    const float* __restrict__ b_content,   // [T, D]
    const float* __restrict__ W_agg,       // [O, 56]
    const float* __restrict__ b_agg,       // [O]
    float* __restrict__ out)               // [O]
{
    __shared__ __align__(16) float bufA[BLOCK * STRA];          // 15360 B : k=0..3 tile
    __shared__ __align__(16) float bufB[BLOCK * STRB];          // 23552 B : k=4..9 tile
    __shared__ float sW[TT * DD * DD];                          // 1372 B
    __shared__ float sb[TT * DD];                               // 196 B
    __shared__ unsigned long long sWt2[(TT + 1) * DD * OP];     // 7168 B : packed-transposed W_agg
    __shared__ float sY[4][OO];                                 // 512 B
    __shared__ int   s_last;

    const int tid = threadIdx.x;
    const int n0  = blockIdx.x * BLOCK;
    const int n   = n0 + tid;
    const bool active = (n < NNODES);

    // ---- one-time weight staging (covered by first __syncthreads) ----
    for (int i = tid; i < TT * DD * DD; i += BLOCK) sW[i] = W_content[i];
    for (int i = tid; i < TT * DD;     i += BLOCK) sb[i] = b_content[i];
    // packed transpose: sWt2[j*OP + p] = (W_agg[2p][j], W_agg[2p+1][j])
    for (int e = tid; e < 56 * OP; e += BLOCK) {
        int j = e >> 4, p = e & 15;
        sWt2[e] = pack2(W_agg[(2 * p) * 56 + j], W_agg[(2 * p + 1) * 56 + j]);
    }

    const char* my_src = (const char*)x_het + (size_t)(n0 + tid) * NODE_B;
    const uint32_t dA = (uint32_t)__cvta_generic_to_shared(bufA) + tid * (STRA * 4);
    const uint32_t dB = (uint32_t)__cvta_generic_to_shared(bufB) + tid * (STRB * 4);
    const size_t type_stride = (size_t)NNODES * NODE_B;

    // prefetch A(0), B(0)
    if (active) {
        #pragma unroll
        for (int c = 0; c < 14; ++c) cp8(dA + c * 8, my_src + c * 8);
    }
    cp_commit();
    if (active) {
        #pragma unroll
        for (int c = 0; c < 21; ++c) cp8(dB + c * 8, my_src + 112 + c * 8);
    }
    cp_commit();

    // packed output accumulators, init with bias
    unsigned long long z2[OP];
    #pragma unroll
    for (int p = 0; p < OP; ++p)
        z2[p] = pack2(__ldg(&b_agg[2 * p]), __ldg(&b_agg[2 * p + 1]));

    #pragma unroll 1
    for (int t = 0; t < TT; ++t) {
        cp_wait<1>();            // A(t) landed (B(t) may still be in flight)
        __syncthreads();

        float Wr[DD * DD], br[DD];
        #pragma unroll
        for (int i = 0; i < DD * DD; ++i) Wr[i] = sW[t * DD * DD + i];
        #pragma unroll
        for (int i = 0; i < DD; ++i) br[i] = sb[t * DD + i];

        float acc[DD];
        #pragma unroll
        for (int o = 0; o < DD; ++o) acc[o] = 0.f;
        float cnt = 0.f;

        // ---- k = 0..3 from bufA ----
        {
            const float* xs = &bufA[tid * STRA];
            #pragma unroll
            for (int k = 0; k < 4; ++k) {
                float xv[DD];
                #pragma unroll
                for (int d = 0; d < DD; ++d) xv[d] = xs[k * DD + d];
                bool nz = false;
                #pragma unroll
                for (int o = 0; o < DD; ++o) {
                    float z = br[o];
                    #pragma unroll
                    for (int d = 0; d < DD; ++d) z = fmaf(xv[d], Wr[o * DD + d], z);
                    acc[o] += fmaxf(z, 0.01f * z);     // LeakyReLU; masked rows all-zero
                    nz = nz || (z != 0.f);
                }
                if (nz) cnt += 1.f;
            }
        }
        __syncthreads();         // done reading bufA

        if (t + 1 < TT) {        // prefetch A(t+1)
            const char* src = my_src + (size_t)(t + 1) * type_stride;
            if (active) {
                #pragma unroll
                for (int c = 0; c < 14; ++c) cp8(dA + c * 8, src + c * 8);
            }
            cp_commit();
            cp_wait<1>();        // B(t) landed (A(t+1) in flight)
        } else {
            cp_wait<0>();        // last type: drain B(t)
        }
        __syncthreads();

        // ---- k = 4..9 from bufB ----
        {
            const float* xs = &bufB[tid * STRB];
            #pragma unroll
            for (int k = 0; k < 6; ++k) {
                float xv[DD];
                #pragma unroll
                for (int d = 0; d < DD; ++d) xv[d] = xs[k * DD + d];
                bool nz = false;
                #pragma unroll
                for (int o = 0; o < DD; ++o) {
                    float z = br[o];
                    #pragma unroll
                    for (int d = 0; d < DD; ++d) z = fmaf(xv[d], Wr[o * DD + d], z);
                    acc[o] += fmaxf(z, 0.01f * z);
                    nz = nz || (z != 0.f);
                }
                if (nz) cnt += 1.f;
            }
        }
        __syncthreads();         // done reading bufB

        if (t + 1 < TT) {        // prefetch B(t+1)
            const char* src = my_src + (size_t)(t + 1) * type_stride;
            if (active) {
                #pragma unroll
                for (int c = 0; c < 21; ++c) cp8(dB + c * 8, src + 112 + c * 8);
            }
            cp_commit();
        }

        // ---- stream this type's het segment into packed z accumulators ----
        const float inv = 1.f / fmaxf(cnt, 1.f);
        const unsigned long long* wrow = &sWt2[t * DD * OP];
        #pragma unroll
        for (int j = 0; j < DD; ++j) {
            float a = acc[j] * inv;
            unsigned long long a2 = pack2(a, a);
            #pragma unroll
            for (int p = 0; p < OP; ++p)
                z2[p] = fma2(a2, wrow[j * OP + p], z2[p]);   // broadcast LDS.64
        }
    }

    // ---- self embedding (node's own type) streamed into z ----
    {
        const int ty = active ? node_types[n] : 0;
        float xn[DD];
        #pragma unroll
        for (int d = 0; d < DD; ++d) xn[d] = active ? x_node[n * DD + d] : 0.f;
        const unsigned long long* wrow = &sWt2[TT * DD * OP];
        #pragma unroll
        for (int o = 0; o < DD; ++o) {
            float z = sb[ty * DD + o];
            #pragma unroll
            for (int d = 0; d < DD; ++d) z = fmaf(xn[d], sW[ty * DD * DD + o * DD + d], z);
            float a = fmaxf(z, 0.01f * z);
            unsigned long long a2 = pack2(a, a);
            #pragma unroll
            for (int p = 0; p < OP; ++p)
                z2[p] = fma2(a2, wrow[o * OP + p], z2[p]);
        }
    }

    // ---- sigmoid + warp butterfly + per-block partial ----
    float y[OO];
    #pragma unroll
    for (int p = 0; p < OP; ++p) {
        float2 v = unpack2(z2[p]);
        y[2 * p]     = active ? (1.f / (1.f + __expf(-v.x))) : 0.f;
        y[2 * p + 1] = active ? (1.f / (1.f + __expf(-v.y))) : 0.f;
    }
    const int wid = tid >> 5, lane = tid & 31;
    #pragma unroll
    for (int o = 0; o < OO; ++o) {
        float v = y[o];
        #pragma unroll
        for (int off = 16; off > 0; off >>= 1)
            v += __shfl_xor_sync(0xffffffffu, v, off);
        if (lane == 0) sY[wid][o] = v;
    }
    __syncthreads();
    if (tid < OO)
        g_partial[blockIdx.x * OO + tid] =
            (sY[0][tid] + sY[1][tid]) + (sY[2][tid] + sY[3][tid]);

    // ---- fused deterministic finale: last block reduces all partials ----
    __threadfence();
    if (tid == 0) {
        unsigned int prev = atomicAdd(&g_count, 1u);
        s_last = (prev == (unsigned)(GRID - 1)) ? 1 : 0;
    }
    __syncthreads();
    if (s_last) {
        __threadfence();
        const volatile float* gp = g_partial;
        const int o = tid & 31;
        const int h = tid >> 5;                 // 0..3
        float a0 = 0.f, a1 = 0.f, a2 = 0.f, a3 = 0.f;
        int b = h;
        for (; b + 12 < GRID; b += 16) {
            a0 += gp[(b     ) * OO + o];
            a1 += gp[(b +  4) * OO + o];
            a2 += gp[(b +  8) * OO + o];
            a3 += gp[(b + 12) * OO + o];
        }
        for (; b < GRID; b += 4) a0 += gp[b * OO + o];
        sY[h][o] = (a0 + a1) + (a2 + a3);
        __syncthreads();
        if (tid < OO)
            out[tid] = ((sY[0][tid] + sY[1][tid]) + (sY[2][tid] + sY[3][tid]))
                       * (1.0f / (float)NNODES);
        if (tid == 0) g_count = 0;              // reset for next graph replay
    }
}

extern "C" void kernel_launch(void* const* d_in, const int* in_sizes, int n_in,
                              void* d_out, int out_size)
{
    const float* x_node    = (const float*)d_in[0];
    const float* x_het     = (const float*)d_in[1];
    const int*   types     = (const int*)  d_in[2];
    const float* W_content = (const float*)d_in[3];
    const float* b_content = (const float*)d_in[4];
    const float* W_agg     = (const float*)d_in[5];
    const float* b_agg     = (const float*)d_in[6];
    float* out = (float*)d_out;

    hetgcn_fused<<<GRID, BLOCK>>>(x_node, x_het, types, W_content, b_content,
                                  W_agg, b_agg, out);
}

// round 6
// speedup vs baseline: 1.2716x; 1.0837x over previous
#include <cuda_runtime.h>
#include <cstdint>

#define NNODES 100000
#define TT 7
#define KK 10
#define DD 7
#define OO 32
#define OP 16                         // 16 packed f32x2 outputs
#define BLOCK 128
#define GRID ((NNODES + BLOCK - 1) / BLOCK)   // 782
#define NODE_B 280                    // bytes per node per type
#define STRA 30                       // floats/node in bufA (28 data + 2 pad) -> 2-way LDS conflicts
#define STRB 42                       // floats/node in bufB (natural)         -> 2-way LDS conflicts
#define CHA 14                        // 8B chunks per node, bufA
#define CHB 21                        // 8B chunks per node, bufB

// deterministic per-block partials + completion counter (zero-init at module load)
__device__ float g_partial[GRID * OO];
__device__ unsigned int g_count;

__device__ __forceinline__ void cp8(uint32_t s, const void* g) {
    asm volatile("cp.async.ca.shared.global [%0], [%1], 8;\n" :: "r"(s), "l"(g));
}
__device__ __forceinline__ void cp_commit() { asm volatile("cp.async.commit_group;\n" ::: "memory"); }
template<int N> __device__ __forceinline__ void cp_wait() { asm volatile("cp.async.wait_group %0;\n" :: "n"(N) : "memory"); }

__device__ __forceinline__ unsigned long long pack2(float lo, float hi) {
    unsigned long long d;
    asm("mov.b64 %0, {%1, %2};" : "=l"(d) : "f"(lo), "f"(hi));
    return d;
}
__device__ __forceinline__ float2 unpack2(unsigned long long v) {
    float2 r;
    asm("mov.b64 {%0, %1}, %2;" : "=f"(r.x), "=f"(r.y) : "l"(v));
    return r;
}
__device__ __forceinline__ unsigned long long fma2(unsigned long long a, unsigned long long b, unsigned long long c) {
    unsigned long long d;
    asm("fma.rn.f32x2 %0, %1, %2, %3;" : "=l"(d) : "l"(a), "l"(b), "l"(c));
    return d;
}

// coalesced staging: flat 8B-chunk index -> (node, offset) with padded smem row
__device__ __forceinline__ void stage_A(uint32_t sbase, const char* tile_src, int rows, int tid) {
    #pragma unroll
    for (int i = 0; i < CHA; ++i) {
        int c = tid + i * BLOCK;                  // consecutive lanes -> consecutive chunks
        int m = c / CHA, off = c - m * CHA;
        if (c < rows * CHA)
            cp8(sbase + m * (STRA * 4) + off * 8, tile_src + (size_t)m * NODE_B + off * 8);
    }
}
__device__ __forceinline__ void stage_B(uint32_t sbase, const char* tile_src, int rows, int tid) {
    #pragma unroll
    for (int i = 0; i < CHB; ++i) {
        int c = tid + i * BLOCK;
        int m = c / CHB, off = c - m * CHB;
        if (c < rows * CHB)
            cp8(sbase + c * 8, tile_src + (size_t)m * NODE_B + 112 + off * 8);  // no pad: flat
    }
}

__global__ __launch_bounds__(BLOCK, 4) void hetgcn_fused(
    const float* __restrict__ x_node,      // [N, D]
    const float* __restrict__ x_het,       // [T, N, K, D]
    const int*   __restrict__ node_types,  // [N]
    const float* __restrict__ W_content,   // [T, D, D]
    const float* __restrict__ b_content,   // [T, D]
    const float* __restrict__ W_agg,       // [O, 56]
    const float* __restrict__ b_agg,       // [O]
    float* __restrict__ out)               // [O]
{
    __shared__ __align__(16) float bufA[BLOCK * STRA];          // 15360 B : k=0..3
    __shared__ __align__(16) float bufB[BLOCK * STRB];          // 21504 B : k=4..9
    __shared__ float sW[TT * DD * DD];                          // 1372 B
    __shared__ float sb[TT * DD];                               // 196 B
    __shared__ unsigned long long sWt2[(TT + 1) * DD * OP];     // 7168 B packed-T W_agg
    __shared__ float sY[4][OO];                                 // 512 B
    __shared__ int   s_last;

    const int tid = threadIdx.x;
    const int n0  = blockIdx.x * BLOCK;
    const int n   = n0 + tid;
    const bool active = (n < NNODES);
    const int rows = min(BLOCK, NNODES - n0);

    // ---- one-time weight staging (covered by first __syncthreads) ----
    for (int i = tid; i < TT * DD * DD; i += BLOCK) sW[i] = W_content[i];
    for (int i = tid; i < TT * DD;     i += BLOCK) sb[i] = b_content[i];
    for (int e = tid; e < 56 * OP; e += BLOCK) {   // sWt2[j*OP+p] = (W[2p][j], W[2p+1][j])
        int j = e >> 4, p = e & 15;
        sWt2[e] = pack2(W_agg[(2 * p) * 56 + j], W_agg[(2 * p + 1) * 56 + j]);
    }

    const char* tile0 = (const char*)x_het + (size_t)n0 * NODE_B;
    const size_t type_stride = (size_t)NNODES * NODE_B;
    const uint32_t sA = (uint32_t)__cvta_generic_to_shared(bufA);
    const uint32_t sB = (uint32_t)__cvta_generic_to_shared(bufB);

    // prefetch A(0), B(0)
    stage_A(sA, tile0, rows, tid); cp_commit();
    stage_B(sB, tile0, rows, tid); cp_commit();

    // packed output accumulators, init with bias
    unsigned long long z2[OP];
    {
        const float2* b2 = (const float2*)b_agg;
        #pragma unroll
        for (int p = 0; p < OP; ++p) {
            float2 b = __ldg(&b2[p]);
            z2[p] = pack2(b.x, b.y);
        }
    }

    #pragma unroll 1
    for (int t = 0; t < TT; ++t) {
        cp_wait<1>();            // A(t) landed (B(t) may still be in flight)
        __syncthreads();

        float Wr[DD * DD], br[DD];
        #pragma unroll
        for (int i = 0; i < DD * DD; ++i) Wr[i] = sW[t * DD * DD + i];
        #pragma unroll
        for (int i = 0; i < DD; ++i) br[i] = sb[t * DD + i];

        float acc[DD];
        #pragma unroll
        for (int o = 0; o < DD; ++o) acc[o] = 0.f;
        float cnt = 0.f;

        // ---- k = 0..3 from bufA ----
        {
            const float* xs = &bufA[tid * STRA];
            #pragma unroll
            for (int k = 0; k < 4; ++k) {
                float xv[DD];
                #pragma unroll
                for (int d = 0; d < DD; ++d) xv[d] = xs[k * DD + d];
                bool nz = false;
                #pragma unroll
                for (int o = 0; o < DD; ++o) {
                    float z = br[o];
                    #pragma unroll
                    for (int d = 0; d < DD; ++d) z = fmaf(xv[d], Wr[o * DD + d], z);
                    acc[o] += fmaxf(z, 0.01f * z);   // LeakyReLU; masked rows all-zero
                    nz = nz || (z != 0.f);
                }
                if (nz) cnt += 1.f;
            }
        }
        __syncthreads();         // done reading bufA

        if (t + 1 < TT) {        // prefetch A(t+1)
            stage_A(sA, tile0 + (size_t)(t + 1) * type_stride, rows, tid);
            cp_commit();
            cp_wait<1>();        // B(t) landed (A(t+1) in flight)
        } else {
            cp_wait<0>();
        }
        __syncthreads();

        // ---- k = 4..9 from bufB ----
        {
            const float* xs = &bufB[tid * STRB];
            #pragma unroll
            for (int k = 0; k < 6; ++k) {
                float xv[DD];
                #pragma unroll
                for (int d = 0; d < DD; ++d) xv[d] = xs[k * DD + d];
                bool nz = false;
                #pragma unroll
                for (int o = 0; o < DD; ++o) {
                    float z = br[o];
                    #pragma unroll
                    for (int d = 0; d < DD; ++d) z = fmaf(xv[d], Wr[o * DD + d], z);
                    acc[o] += fmaxf(z, 0.01f * z);
                    nz = nz || (z != 0.f);
                }
                if (nz) cnt += 1.f;
            }
        }
        __syncthreads();         // done reading bufB

        if (t + 1 < TT) {        // prefetch B(t+1)
            stage_B(sB, tile0 + (size_t)(t + 1) * type_stride, rows, tid);
            cp_commit();
        }

        // ---- stream this type's het segment into packed z accumulators ----
        const float inv = 1.f / fmaxf(cnt, 1.f);
        const unsigned long long* wrow = &sWt2[t * DD * OP];
        #pragma unroll
        for (int j = 0; j < DD; ++j) {
            float a = acc[j] * inv;
            unsigned long long a2 = pack2(a, a);
            #pragma unroll
            for (int p = 0; p < OP; ++p)
                z2[p] = fma2(a2, wrow[j * OP + p], z2[p]);   // broadcast LDS.64
        }
    }

    // ---- self embedding (node's own type) streamed into z ----
    {
        const int ty = active ? node_types[n] : 0;
        float xn[DD];
        #pragma unroll
        for (int d = 0; d < DD; ++d) xn[d] = active ? x_node[n * DD + d] : 0.f;
        const unsigned long long* wrow = &sWt2[TT * DD * OP];
        #pragma unroll
        for (int o = 0; o < DD; ++o) {
            float z = sb[ty * DD + o];
            #pragma unroll
            for (int d = 0; d < DD; ++d) z = fmaf(xn[d], sW[ty * DD * DD + o * DD + d], z);
            float a = fmaxf(z, 0.01f * z);
            unsigned long long a2 = pack2(a, a);
            #pragma unroll
            for (int p = 0; p < OP; ++p)
                z2[p] = fma2(a2, wrow[o * OP + p], z2[p]);
        }
    }

    // ---- sigmoid + warp butterfly + per-block partial ----
    float y[OO];
    #pragma unroll
    for (int p = 0; p < OP; ++p) {
        float2 v = unpack2(z2[p]);
        y[2 * p]     = active ? (1.f / (1.f + __expf(-v.x))) : 0.f;
        y[2 * p + 1] = active ? (1.f / (1.f + __expf(-v.y))) : 0.f;
    }
    const int wid = tid >> 5, lane = tid & 31;
    #pragma unroll
    for (int o = 0; o < OO; ++o) {
        float v = y[o];
        #pragma unroll
        for (int off = 16; off > 0; off >>= 1)
            v += __shfl_xor_sync(0xffffffffu, v, off);
        if (lane == 0) sY[wid][o] = v;
    }
    __syncthreads();
    if (tid < OO)
        g_partial[blockIdx.x * OO + tid] =
            (sY[0][tid] + sY[1][tid]) + (sY[2][tid] + sY[3][tid]);

    // ---- fused deterministic finale: last block reduces all partials ----
    __threadfence();
    if (tid == 0) {
        unsigned int prev = atomicAdd(&g_count, 1u);
        s_last = (prev == (unsigned)(GRID - 1)) ? 1 : 0;
    }
    __syncthreads();
    if (s_last) {
        __threadfence();
        const volatile float* gp = g_partial;
        const int o = tid & 31;
        const int h = tid >> 5;                 // 0..3
        float a0 = 0.f, a1 = 0.f, a2 = 0.f, a3 = 0.f;
        int b = h;
        for (; b + 12 < GRID; b += 16) {
            a0 += gp[(b     ) * OO + o];
            a1 += gp[(b +  4) * OO + o];
            a2 += gp[(b +  8) * OO + o];
            a3 += gp[(b + 12) * OO + o];
        }
        for (; b < GRID; b += 4) a0 += gp[b * OO + o];
        sY[h][o] = (a0 + a1) + (a2 + a3);
        __syncthreads();
        if (tid < OO)
            out[tid] = ((sY[0][tid] + sY[1][tid]) + (sY[2][tid] + sY[3][tid]))
                       * (1.0f / (float)NNODES);
        if (tid == 0) g_count = 0;              // reset for next graph replay
    }
}

extern "C" void kernel_launch(void* const* d_in, const int* in_sizes, int n_in,
                              void* d_out, int out_size)
{
    const float* x_node    = (const float*)d_in[0];
    const float* x_het     = (const float*)d_in[1];
    const int*   types     = (const int*)  d_in[2];
    const float* W_content = (const float*)d_in[3];
    const float* b_content = (const float*)d_in[4];
    const float* W_agg     = (const float*)d_in[5];
    const float* b_agg     = (const float*)d_in[6];
    float* out = (float*)d_out;

    hetgcn_fused<<<GRID, BLOCK>>>(x_node, x_het, types, W_content, b_content,
                                  W_agg, b_agg, out);
}

// round 7
// speedup vs baseline: 1.5845x; 1.2460x over previous
#include <cuda_runtime.h>
#include <cstdint>

#define NNODES 100000
#define TT 7
#define KK 10
#define DD 7
#define OO 32
#define OP 16                         // 16 packed f32x2 outputs
#define BLOCK 128
#define GRID ((NNODES + BLOCK - 1) / BLOCK)   // 782
#define NODE_B 280                    // bytes per node per type
#define STRA 30                       // floats/node in bufA (28 data + 2 pad)
#define STRB 42                       // floats/node in bufB (natural)

// deterministic per-block partials + completion counter (zero-init at module load)
__device__ float g_partial[GRID * OO];
__device__ unsigned int g_count;

__device__ __forceinline__ void cp8(uint32_t s, const void* g) {
    asm volatile("cp.async.ca.shared.global [%0], [%1], 8;\n" :: "r"(s), "l"(g));
}
__device__ __forceinline__ void cp_commit() { asm volatile("cp.async.commit_group;\n" ::: "memory"); }
template<int N> __device__ __forceinline__ void cp_wait() { asm volatile("cp.async.wait_group %0;\n" :: "n"(N) : "memory"); }

__device__ __forceinline__ unsigned long long pack2(float lo, float hi) {
    unsigned long long d;
    asm("mov.b64 %0, {%1, %2};" : "=l"(d) : "f"(lo), "f"(hi));
    return d;
}
__device__ __forceinline__ float2 unpack2(unsigned long long v) {
    float2 r;
    asm("mov.b64 {%0, %1}, %2;" : "=f"(r.x), "=f"(r.y) : "l"(v));
    return r;
}
__device__ __forceinline__ unsigned long long fma2(unsigned long long a, unsigned long long b, unsigned long long c) {
    unsigned long long d;
    asm("fma.rn.f32x2 %0, %1, %2, %3;" : "=l"(d) : "l"(a), "l"(b), "l"(c));
    return d;
}

// load 7 floats from smem with float2 vectorization; base is compile-time
__device__ __forceinline__ void load7(const float* xs, int base, float xv[DD]) {
    if ((base & 1) == 0) {
        const float2* p = (const float2*)(xs + base);
        float2 a = p[0], b = p[1], c = p[2];
        xv[0]=a.x; xv[1]=a.y; xv[2]=b.x; xv[3]=b.y; xv[4]=c.x; xv[5]=c.y;
        xv[6]=xs[base + 6];
    } else {
        xv[0]=xs[base];
        const float2* p = (const float2*)(xs + base + 1);
        float2 a = p[0], b = p[1], c = p[2];
        xv[1]=a.x; xv[2]=a.y; xv[3]=b.x; xv[4]=b.y; xv[5]=c.x; xv[6]=c.y;
    }
}

__global__ __launch_bounds__(BLOCK, 4) void hetgcn_fused(
    const float* __restrict__ x_node,      // [N, D]
    const float* __restrict__ x_het,       // [T, N, K, D]
    const int*   __restrict__ node_types,  // [N]
    const float* __restrict__ W_content,   // [T, D, D]
    const float* __restrict__ b_content,   // [T, D]
    const float* __restrict__ W_agg,       // [O, 56]
    const float* __restrict__ b_agg,       // [O]
    float* __restrict__ out)               // [O]
{
    __shared__ __align__(16) float bufA[BLOCK * STRA];          // 15360 B : k=0..3
    __shared__ __align__(16) float bufB[BLOCK * STRB];          // 21504 B : k=4..9
    __shared__ float sW[TT * DD * DD];                          // 1372 B
    __shared__ float sb[TT * DD];                               // 196 B
    __shared__ unsigned long long sWt2[(TT + 1) * DD * OP];     // 7168 B packed-T W_agg
    __shared__ float sY[4][OO];                                 // 512 B
    __shared__ int   s_last;

    const int tid = threadIdx.x;
    const int n0  = blockIdx.x * BLOCK;
    const int n   = n0 + tid;
    const bool active = (n < NNODES);
    const int rows = min(BLOCK, NNODES - n0);

    // ---- one-time weight staging (covered by first __syncthreads) ----
    for (int i = tid; i < TT * DD * DD; i += BLOCK) sW[i] = W_content[i];
    for (int i = tid; i < TT * DD;     i += BLOCK) sb[i] = b_content[i];
    for (int e = tid; e < 56 * OP; e += BLOCK) {   // sWt2[j*OP+p] = (W[2p][j], W[2p+1][j])
        int j = e >> 4, p = e & 15;
        sWt2[e] = pack2(W_agg[(2 * p) * 56 + j], W_agg[(2 * p + 1) * 56 + j]);
    }

    // ---- division-free staging precompute (ONCE per thread) ----
    // A: 112 threads, 8 nodes/iter, 16 iters;  B: 126 threads, 6 nodes/iter, 22 iters
    const int m0A = tid / 14, offA = tid - m0A * 14;
    const int m0B = tid / 21, offB = tid - m0B * 21;
    const int iA_max = (tid < 112) ? ((rows - m0A + 7) >> 3) : 0;
    const int iB_max = (tid < 126) ? ((rows - m0B + 5) / 6)  : 0;

    const char* tile0 = (const char*)x_het + (size_t)n0 * NODE_B;
    const size_t type_stride = (size_t)NNODES * NODE_B;
    const uint32_t sAaddr = (uint32_t)__cvta_generic_to_shared(bufA) + m0A * (STRA * 4) + offA * 8;
    const uint32_t sBaddr = (uint32_t)__cvta_generic_to_shared(bufB) + m0B * (STRB * 4) + offB * 8;
    const int gA0 = m0A * NODE_B + offA * 8;
    const int gB0 = m0B * NODE_B + 112 + offB * 8;

    // prefetch A(0), B(0)
    {
        const char* gA = tile0 + gA0;
        #pragma unroll
        for (int i = 0; i < 16; ++i) if (i < iA_max) cp8(sAaddr + i * 960, gA + i * 2240);
        cp_commit();
        const char* gB = tile0 + gB0;
        #pragma unroll
        for (int i = 0; i < 22; ++i) if (i < iB_max) cp8(sBaddr + i * 1008, gB + i * 1680);
        cp_commit();
    }

    // packed output accumulators, init with bias
    unsigned long long z2[OP];
    {
        const float2* b2 = (const float2*)b_agg;
        #pragma unroll
        for (int p = 0; p < OP; ++p) {
            float2 b = __ldg(&b2[p]);
            z2[p] = pack2(b.x, b.y);
        }
    }

    #pragma unroll 1
    for (int t = 0; t < TT; ++t) {
        cp_wait<1>();            // A(t) landed (B(t) may still be in flight)
        __syncthreads();

        float Wr[DD * DD], br[DD];
        #pragma unroll
        for (int i = 0; i < DD * DD; ++i) Wr[i] = sW[t * DD * DD + i];
        #pragma unroll
        for (int i = 0; i < DD; ++i) br[i] = sb[t * DD + i];

        float acc[DD];
        #pragma unroll
        for (int o = 0; o < DD; ++o) acc[o] = 0.f;
        float cnt = 0.f;

        // ---- k = 0..3 from bufA ----
        {
            const float* xs = &bufA[tid * STRA];
            #pragma unroll
            for (int k = 0; k < 4; ++k) {
                float xv[DD];
                load7(xs, k * DD, xv);
                float s = 0.f;
                #pragma unroll
                for (int o = 0; o < DD; ++o) {
                    float z = br[o];
                    #pragma unroll
                    for (int d = 0; d < DD; ++d) z = fmaf(xv[d], Wr[o * DD + d], z);
                    acc[o] += fmaxf(z, 0.01f * z);   // LeakyReLU; masked rows all-zero
                    s += fabsf(z);                   // nz <=> sum|z| != 0 (exact)
                }
                if (s != 0.f) cnt += 1.f;
            }
        }
        __syncthreads();         // done reading bufA

        if (t + 1 < TT) {        // prefetch A(t+1)
            const char* gA = tile0 + (size_t)(t + 1) * type_stride + gA0;
            #pragma unroll
            for (int i = 0; i < 16; ++i) if (i < iA_max) cp8(sAaddr + i * 960, gA + i * 2240);
            cp_commit();
            cp_wait<1>();        // B(t) landed (A(t+1) in flight)
        } else {
            cp_wait<0>();
        }
        __syncthreads();

        // ---- k = 4..9 from bufB ----
        {
            const float* xs = &bufB[tid * STRB];
            #pragma unroll
            for (int k = 0; k < 6; ++k) {
                float xv[DD];
                load7(xs, k * DD, xv);
                float s = 0.f;
                #pragma unroll
                for (int o = 0; o < DD; ++o) {
                    float z = br[o];
                    #pragma unroll
                    for (int d = 0; d < DD; ++d) z = fmaf(xv[d], Wr[o * DD + d], z);
                    acc[o] += fmaxf(z, 0.01f * z);
                    s += fabsf(z);
                }
                if (s != 0.f) cnt += 1.f;
            }
        }
        __syncthreads();         // done reading bufB

        if (t + 1 < TT) {        // prefetch B(t+1)
            const char* gB = tile0 + (size_t)(t + 1) * type_stride + gB0;
            #pragma unroll
            for (int i = 0; i < 22; ++i) if (i < iB_max) cp8(sBaddr + i * 1008, gB + i * 1680);
            cp_commit();
        }

        // ---- stream this type's het segment into packed z accumulators ----
        const float inv = 1.f / fmaxf(cnt, 1.f);
        const unsigned long long* wrow = &sWt2[t * DD * OP];
        #pragma unroll
        for (int j = 0; j < DD; ++j) {
            float a = acc[j] * inv;
            unsigned long long a2 = pack2(a, a);
            #pragma unroll
            for (int p = 0; p < OP; ++p)
                z2[p] = fma2(a2, wrow[j * OP + p], z2[p]);   // broadcast LDS.64
        }
    }

    // ---- self embedding (node's own type) streamed into z ----
    {
        const int ty = active ? node_types[n] : 0;
        float xn[DD];
        #pragma unroll
        for (int d = 0; d < DD; ++d) xn[d] = active ? x_node[n * DD + d] : 0.f;
        const unsigned long long* wrow = &sWt2[TT * DD * OP];
        #pragma unroll
        for (int o = 0; o < DD; ++o) {
            float z = sb[ty * DD + o];
            #pragma unroll
            for (int d = 0; d < DD; ++d) z = fmaf(xn[d], sW[ty * DD * DD + o * DD + d], z);
            float a = fmaxf(z, 0.01f * z);
            unsigned long long a2 = pack2(a, a);
            #pragma unroll
            for (int p = 0; p < OP; ++p)
                z2[p] = fma2(a2, wrow[o * OP + p], z2[p]);
        }
    }

    // ---- sigmoid + warp butterfly + per-block partial ----
    float y[OO];
    #pragma unroll
    for (int p = 0; p < OP; ++p) {
        float2 v = unpack2(z2[p]);
        y[2 * p]     = active ? (1.f / (1.f + __expf(-v.x))) : 0.f;
        y[2 * p + 1] = active ? (1.f / (1.f + __expf(-v.y))) : 0.f;
    }
    const int wid = tid >> 5, lane = tid & 31;
    #pragma unroll
    for (int o = 0; o < OO; ++o) {
        float v = y[o];
        #pragma unroll
        for (int off = 16; off > 0; off >>= 1)
            v += __shfl_xor_sync(0xffffffffu, v, off);
        if (lane == 0) sY[wid][o] = v;
    }
    __syncthreads();
    if (tid < OO)
        g_partial[blockIdx.x * OO + tid] =
            (sY[0][tid] + sY[1][tid]) + (sY[2][tid] + sY[3][tid]);

    // ---- fused deterministic finale: last block reduces all partials ----
    __threadfence();
    if (tid == 0) {
        unsigned int prev = atomicAdd(&g_count, 1u);
        s_last = (prev == (unsigned)(GRID - 1)) ? 1 : 0;
    }
    __syncthreads();
    if (s_last) {
        __threadfence();
        const volatile float* gp = g_partial;
        const int o = tid & 31;
        const int h = tid >> 5;                 // 0..3
        float a0 = 0.f, a1 = 0.f, a2 = 0.f, a3 = 0.f;
        int b = h;
        for (; b + 12 < GRID; b += 16) {
            a0 += gp[(b     ) * OO + o];
            a1 += gp[(b +  4) * OO + o];
            a2 += gp[(b +  8) * OO + o];
            a3 += gp[(b + 12) * OO + o];
        }
        for (; b < GRID; b += 4) a0 += gp[b * OO + o];
        sY[h][o] = (a0 + a1) + (a2 + a3);
        __syncthreads();
        if (tid < OO)
            out[tid] = ((sY[0][tid] + sY[1][tid]) + (sY[2][tid] + sY[3][tid]))
                       * (1.0f / (float)NNODES);
        if (tid == 0) g_count = 0;              // reset for next graph replay
    }
}

extern "C" void kernel_launch(void* const* d_in, const int* in_sizes, int n_in,
                              void* d_out, int out_size)
{
    const float* x_node    = (const float*)d_in[0];
    const float* x_het     = (const float*)d_in[1];
    const int*   types     = (const int*)  d_in[2];
    const float* W_content = (const float*)d_in[3];
    const float* b_content = (const float*)d_in[4];
    const float* W_agg     = (const float*)d_in[5];
    const float* b_agg     = (const float*)d_in[6];
    float* out = (float*)d_out;

    hetgcn_fused<<<GRID, BLOCK>>>(x_node, x_het, types, W_content, b_content,
                                  W_agg, b_agg, out);
}